// round 12
// baseline (speedup 1.0000x reference)
#include <cuda_runtime.h>
#include <cuda_bf16.h>
#include <mma.h>
#include <cstdint>

using namespace nvcuda;

#define BB    2
#define CC    64
#define NPOS  131072
#define HEADS 4
#define DHEAD 32
#define HID   128
#define TPB   256
#define POSB  128
#define LDX   72      // A-tile leading dim (x), elements
#define LDQ   136     // A-tile leading dim (q), elements

typedef unsigned long long u64;
typedef unsigned int       u32;

// ---------------- device scratch ----------------
__device__ float g_ctx[BB * HEADS * DHEAD * DHEAD];
__device__ float g_Z[BB * HEADS * DHEAD];
__device__ __nv_bfloat16 g_Mh[BB][HID * CC];   // M split hi, [i][o] row-major
__device__ __nv_bfloat16 g_Ml[BB][HID * CC];   // M split lo

// ---------------- f32x2 helpers (stage B) ----------------
__device__ __forceinline__ u64 ffma2(u64 a, u64 b, u64 c) {
    u64 d; asm("fma.rn.f32x2 %0, %1, %2, %3;" : "=l"(d) : "l"(a), "l"(b), "l"(c)); return d;
}
__device__ __forceinline__ u64 fadd2(u64 a, u64 b) {
    u64 d; asm("add.rn.f32x2 %0, %1, %2;" : "=l"(d) : "l"(a), "l"(b)); return d;
}
__device__ __forceinline__ float hsum2(u64 a) {
    float lo, hi; asm("mov.b64 {%0,%1}, %2;" : "=f"(lo), "=f"(hi) : "l"(a)); return lo + hi;
}

// ---------------- kernel 0: zero accumulators ----------------
__global__ void la_zero_kernel() {
    int i = blockIdx.x * blockDim.x + threadIdx.x;
    if (i < BB * HEADS * DHEAD * DHEAD) g_ctx[i] = 0.f;
    if (i < BB * HEADS * DHEAD)         g_Z[i]   = 0.f;
}

// stage B: ctx[d][e] += sum_pos ek[d][pos]*vv[e][pos]; Z[d] += sum ek. 256 threads.
__device__ __forceinline__ void stageB(const float* ek, const float* vv, int bb, int h, int t) {
    const int d_own = t >> 3, e0 = t & 7;
    u64 a0 = 0, a1 = 0, a2 = 0, a3 = 0, za = 0;
    const float* ekr = ek + d_own * 132;
#pragma unroll 4
    for (int tt = 0; tt < POSB; tt += 4) {
        ulonglong2 ap  = *(const ulonglong2*)(ekr + tt);
        ulonglong2 bv0 = *(const ulonglong2*)(vv + (e0     ) * 132 + tt);
        ulonglong2 bv1 = *(const ulonglong2*)(vv + (e0 +  8) * 132 + tt);
        ulonglong2 bv2 = *(const ulonglong2*)(vv + (e0 + 16) * 132 + tt);
        ulonglong2 bv3 = *(const ulonglong2*)(vv + (e0 + 24) * 132 + tt);
        a0 = ffma2(ap.x, bv0.x, a0); a0 = ffma2(ap.y, bv0.y, a0);
        a1 = ffma2(ap.x, bv1.x, a1); a1 = ffma2(ap.y, bv1.y, a1);
        a2 = ffma2(ap.x, bv2.x, a2); a2 = ffma2(ap.y, bv2.y, a2);
        a3 = ffma2(ap.x, bv3.x, a3); a3 = ffma2(ap.y, bv3.y, a3);
        if (e0 == 0) za = fadd2(za, fadd2(ap.x, ap.y));
    }
    float* cb = g_ctx + (size_t)((bb * HEADS + h) * DHEAD + d_own) * DHEAD;
    atomicAdd(cb + e0,      hsum2(a0));
    atomicAdd(cb + e0 +  8, hsum2(a1));
    atomicAdd(cb + e0 + 16, hsum2(a2));
    atomicAdd(cb + e0 + 24, hsum2(a3));
    if (e0 == 0) atomicAdd(g_Z + (bb * HEADS + h) * DHEAD + d_own, hsum2(za));
}

// split a float into bf16 hi + residual
__device__ __forceinline__ void bsplit(float v, __nv_bfloat16& h, __nv_bfloat16& l) {
    h = __float2bfloat16_rn(v);
    l = __float2bfloat16_rn(v - __bfloat162float(h));
}

// ================= pass1: LN + wmma [K;V] GEMM + ctx/Z =================
// smem bytes:
#define P1_XH 0                      // 128*72*2 = 18432
#define P1_XL 18432
#define P1_WH 36864                  // 256*64*2 = 32768
#define P1_WL 69632
#define P1_EK 102400                 // 32*132*4 = 16896
#define P1_VV 119296
#define P1_G1 136192
#define P1_B1 136448
#define P1_BYTES 136704

__global__ __launch_bounds__(TPB, 1)
void la_pass1_kernel(const float* __restrict__ x, const float* __restrict__ g1,
                     const float* __restrict__ b1, const float* __restrict__ wqkv) {
    extern __shared__ char smem[];
    __nv_bfloat16* xh = (__nv_bfloat16*)(smem + P1_XH);
    __nv_bfloat16* xl = (__nv_bfloat16*)(smem + P1_XL);
    __nv_bfloat16* wh = (__nv_bfloat16*)(smem + P1_WH);
    __nv_bfloat16* wl = (__nv_bfloat16*)(smem + P1_WL);
    float* ekf = (float*)(smem + P1_EK);
    float* vvf = (float*)(smem + P1_VV);
    float* g1s = (float*)(smem + P1_G1);
    float* b1s = (float*)(smem + P1_B1);

    const int t   = threadIdx.x;
    const int wid = t >> 5;
    const int bb   = blockIdx.y;
    const int pos0 = blockIdx.x * POSB;

    float xr[64]; float mean = 0.f, rstd = 0.f;
    if (t < 128) {
        const float* xb = x + (size_t)bb * CC * NPOS + pos0 + t;
        float s = 0.f, s2 = 0.f;
#pragma unroll
        for (int c = 0; c < 64; c++) {
            float v = __ldg(xb + (size_t)c * NPOS);
            xr[c] = v; s += v; s2 += v * v;
        }
        mean = s * (1.f / 64.f);
        rstd = rsqrtf(s2 * (1.f / 64.f) - mean * mean + 1e-5f);
    } else {
        int tw = t - 128;
        if (tw < 64) { g1s[tw] = g1[tw]; b1s[tw] = b1[tw]; }
        // stage W rows 128..383 (K then V), split bf16, [row][k] with ld 64
#pragma unroll 8
        for (int i = 0; i < 64; i++) {
            int idx = tw + i * 128;       // pair index, 0..8191
            int row = idx >> 5, kp = idx & 31;
            float2 wv = *(const float2*)(wqkv + (size_t)(128 + row) * 64 + 2 * kp);
            __nv_bfloat16 h0, l0, h1, l1;
            bsplit(wv.x, h0, l0); bsplit(wv.y, h1, l1);
            wh[row * 64 + 2 * kp] = h0; wh[row * 64 + 2 * kp + 1] = h1;
            wl[row * 64 + 2 * kp] = l0; wl[row * 64 + 2 * kp + 1] = l1;
        }
    }
    __syncthreads();

    if (t < 128) {          // normalize + split + store A tiles (pos-major, ld 72)
#pragma unroll
        for (int c = 0; c < 64; c++) {
            float v = (xr[c] - mean) * rstd * g1s[c] + b1s[c];
            __nv_bfloat16 h, l; bsplit(v, h, l);
            xh[t * LDX + c] = h; xl[t * LDX + c] = l;
        }
    }
    __syncthreads();

    // hoist A fragments (4 k-tiles, hi+lo)
    wmma::fragment<wmma::matrix_a, 16, 16, 16, __nv_bfloat16, wmma::row_major> fAh[4], fAl[4];
#pragma unroll
    for (int kt = 0; kt < 4; kt++) {
        wmma::load_matrix_sync(fAh[kt], xh + wid * 16 * LDX + kt * 16, LDX);
        wmma::load_matrix_sync(fAl[kt], xl + wid * 16 * LDX + kt * 16, LDX);
    }

    for (int h = 0; h < HEADS; h++) {
        wmma::fragment<wmma::accumulator, 16, 16, 16, float> accK[2], accV[2];
#pragma unroll
        for (int nt = 0; nt < 2; nt++) { wmma::fill_fragment(accK[nt], 0.f); wmma::fill_fragment(accV[nt], 0.f); }
#pragma unroll
        for (int kt = 0; kt < 4; kt++) {
#pragma unroll
            for (int nt = 0; nt < 2; nt++) {
                wmma::fragment<wmma::matrix_b, 16, 16, 16, __nv_bfloat16, wmma::col_major> fBh, fBl;
                const __nv_bfloat16* bk = wh + (size_t)(h * 32 + nt * 16) * 64 + kt * 16;
                const __nv_bfloat16* bkl = wl + (size_t)(h * 32 + nt * 16) * 64 + kt * 16;
                wmma::load_matrix_sync(fBh, bk, 64);
                wmma::load_matrix_sync(fBl, bkl, 64);
                wmma::mma_sync(accK[nt], fAh[kt], fBh, accK[nt]);
                wmma::mma_sync(accK[nt], fAh[kt], fBl, accK[nt]);
                wmma::mma_sync(accK[nt], fAl[kt], fBh, accK[nt]);
                const __nv_bfloat16* bv = wh + (size_t)(128 + h * 32 + nt * 16) * 64 + kt * 16;
                const __nv_bfloat16* bvl = wl + (size_t)(128 + h * 32 + nt * 16) * 64 + kt * 16;
                wmma::load_matrix_sync(fBh, bv, 64);
                wmma::load_matrix_sync(fBl, bvl, 64);
                wmma::mma_sync(accV[nt], fAh[kt], fBh, accV[nt]);
                wmma::mma_sync(accV[nt], fAh[kt], fBl, accV[nt]);
                wmma::mma_sync(accV[nt], fAl[kt], fBh, accV[nt]);
            }
        }
#pragma unroll
        for (int nt = 0; nt < 2; nt++) {
            wmma::store_matrix_sync(ekf + nt * 16 * 132 + wid * 16, accK[nt], 132, wmma::mem_col_major);
            wmma::store_matrix_sync(vvf + nt * 16 * 132 + wid * 16, accV[nt], 132, wmma::mem_col_major);
        }
        __syncthreads();
        // exp on ek
#pragma unroll
        for (int j = 0; j < 16; j++) {
            int idx = t + j * 256;
            int row = idx >> 7, p = idx & 127;
            ekf[row * 132 + p] = __expf(ekf[row * 132 + p]);
        }
        __syncthreads();
        stageB(ekf, vvf, bb, h, t);
        __syncthreads();
    }
}

// ---------------- kernel 2: fold -> split-bf16 M [i][o] ----------------
__global__ void la_fold_kernel(const float* __restrict__ wout) {
    int bb = blockIdx.x;
    for (int idx = threadIdx.x; idx < HID * CC; idx += blockDim.x) {
        int i = idx >> 6, o = idx & 63;
        int h = i >> 5,   d = i & 31;
        const float* cp = g_ctx + (size_t)((bb * HEADS + h) * DHEAD + d) * DHEAD;
        const float* wp = wout + (size_t)o * HID + h * DHEAD;
        float acc = 0.f;
#pragma unroll
        for (int e = 0; e < 32; e++) acc += wp[e] * cp[e];
        float m = acc / g_Z[(bb * HEADS + h) * DHEAD + d];
        __nv_bfloat16 mh, ml; bsplit(m, mh, ml);
        g_Mh[bb][i * 64 + o] = mh;
        g_Ml[bb][i * 64 + o] = ml;
    }
}

// ===== pass2: LN + Q GEMM + register softmax + q@M GEMM + LN2 =====
#define P2_XH  0          // x A-tiles 18432; later overlaid by q-hi (34816 spans XH+XL)
#define P2_XL  18432
#define P2_QH  0          // q hi A-tile 128*136*2 = 34816
#define P2_QL  34816      // q lo A-tile 34816 -> ends 69632
#define P2_WQH 36864      // WQ hi 128*64*2 = 16384 (dead before q tiles written? NO: inside QL!)
#define P2_WQL 53248
#define P2_EKQ 69632      // 128*132*4 = 67584; ys overlays
#define P2_PAR 137216     // 5*64 floats = 1280
#define P2_MH  138496     // M hi 16384
#define P2_ML  154880     // M lo 16384
#define P2_BYTES 171264

__global__ __launch_bounds__(TPB, 1)
void la_pass2_kernel(const float* __restrict__ x, const float* __restrict__ g1,
                     const float* __restrict__ b1, const float* __restrict__ wqkv,
                     const float* __restrict__ bout, const float* __restrict__ g2,
                     const float* __restrict__ b2, float* __restrict__ out) {
    extern __shared__ char smem[];
    __nv_bfloat16* xh  = (__nv_bfloat16*)(smem + P2_XH);
    __nv_bfloat16* xl  = (__nv_bfloat16*)(smem + P2_XL);
    __nv_bfloat16* qh  = (__nv_bfloat16*)(smem + P2_QH);
    __nv_bfloat16* ql  = (__nv_bfloat16*)(smem + P2_QL);
    __nv_bfloat16* wqh = (__nv_bfloat16*)(smem + P2_WQH);
    __nv_bfloat16* wql = (__nv_bfloat16*)(smem + P2_WQL);
    __nv_bfloat16* mh  = (__nv_bfloat16*)(smem + P2_MH);
    __nv_bfloat16* ml  = (__nv_bfloat16*)(smem + P2_ML);
    float* ekq = (float*)(smem + P2_EKQ);
    float* ys  = (float*)(smem + P2_EKQ);          // reuse after softmax
    float* g1s = (float*)(smem + P2_PAR);
    float* b1s = g1s + 64;
    float* g2s = b1s + 64;
    float* b2s = g2s + 64;
    float* bos = b2s + 64;

    const int t   = threadIdx.x;
    const int wid = t >> 5;
    const int bb   = blockIdx.y;
    const int pos0 = blockIdx.x * POSB;

    float xr[64]; float mean = 0.f, rstd = 0.f;
    if (t < 128) {
        const float* xb = x + (size_t)bb * CC * NPOS + pos0 + t;
        float s = 0.f, s2 = 0.f;
#pragma unroll
        for (int c = 0; c < 64; c++) {
            float v = __ldg(xb + (size_t)c * NPOS);
            xr[c] = v; s += v; s2 += v * v;
        }
        mean = s * (1.f / 64.f);
        rstd = rsqrtf(s2 * (1.f / 64.f) - mean * mean + 1e-5f);
    } else {
        int tw = t - 128;
        if (tw < 64) {
            g1s[tw] = g1[tw]; b1s[tw] = b1[tw];
            g2s[tw] = g2[tw]; b2s[tw] = b2[tw]; bos[tw] = bout[tw];
        }
        // stage W_Q rows 0..127 split bf16
#pragma unroll 8
        for (int i = 0; i < 32; i++) {
            int idx = tw + i * 128;       // pair index 0..4095
            int row = idx >> 5, kp = idx & 31;
            float2 wv = *(const float2*)(wqkv + (size_t)row * 64 + 2 * kp);
            __nv_bfloat16 h0, l0, h1, l1;
            bsplit(wv.x, h0, l0); bsplit(wv.y, h1, l1);
            wqh[row * 64 + 2 * kp] = h0; wqh[row * 64 + 2 * kp + 1] = h1;
            wql[row * 64 + 2 * kp] = l0; wql[row * 64 + 2 * kp + 1] = l1;
        }
        // stage M tiles (already split in global)
#pragma unroll
        for (int i = 0; i < 8; i++) {
            int idx = tw + i * 128;       // uint4 index, 0..1023 per buf
            ((uint4*)mh)[idx] = ((const uint4*)g_Mh[bb])[idx];
            ((uint4*)ml)[idx] = ((const uint4*)g_Ml[bb])[idx];
        }
    }
    __syncthreads();

    if (t < 128) {
#pragma unroll
        for (int c = 0; c < 64; c++) {
            float v = (xr[c] - mean) * rstd * g1s[c] + b1s[c];
            __nv_bfloat16 h, l; bsplit(v, h, l);
            xh[t * LDX + c] = h; xl[t * LDX + c] = l;
        }
    }
    __syncthreads();

    // ---- Q GEMM: logits [128 q-rows][128 pos] -> ekq col-major [row][pos] ----
    {
        wmma::fragment<wmma::matrix_a, 16, 16, 16, __nv_bfloat16, wmma::row_major> fAh[4], fAl[4];
#pragma unroll
        for (int kt = 0; kt < 4; kt++) {
            wmma::load_matrix_sync(fAh[kt], xh + wid * 16 * LDX + kt * 16, LDX);
            wmma::load_matrix_sync(fAl[kt], xl + wid * 16 * LDX + kt * 16, LDX);
        }
#pragma unroll
        for (int nt = 0; nt < 8; nt++) {
            wmma::fragment<wmma::accumulator, 16, 16, 16, float> acc;
            wmma::fill_fragment(acc, 0.f);
#pragma unroll
            for (int kt = 0; kt < 4; kt++) {
                wmma::fragment<wmma::matrix_b, 16, 16, 16, __nv_bfloat16, wmma::col_major> fBh, fBl;
                wmma::load_matrix_sync(fBh, wqh + (size_t)(nt * 16) * 64 + kt * 16, 64);
                wmma::load_matrix_sync(fBl, wql + (size_t)(nt * 16) * 64 + kt * 16, 64);
                wmma::mma_sync(acc, fAh[kt], fBh, acc);
                wmma::mma_sync(acc, fAh[kt], fBl, acc);
                wmma::mma_sync(acc, fAl[kt], fBh, acc);
            }
            wmma::store_matrix_sync(ekq + nt * 16 * 132 + wid * 16, acc, 132, wmma::mem_col_major);
        }
    }
    __syncthreads();

    // ---- softmax per position per head; write q A-tiles (overlays x/WQ region) ----
    if (t < 128) {
        float qbuf[HID];
#pragma unroll
        for (int h = 0; h < HEADS; h++) {
            float qv[32];
            float mx = -1e30f;
#pragma unroll
            for (int d = 0; d < 32; d++) {
                qv[d] = ekq[(h * 32 + d) * 132 + t];
                mx = fmaxf(mx, qv[d]);
            }
            float ss = 0.f;
#pragma unroll
            for (int d = 0; d < 32; d++) { qv[d] = __expf(qv[d] - mx); ss += qv[d]; }
            float sc = 0.17677669529663687f / ss;
#pragma unroll
            for (int d = 0; d < 32; d++) qbuf[h * 32 + d] = qv[d] * sc;
        }
        __syncthreads();                 // everyone done reading ekq/x tiles
#pragma unroll
        for (int c = 0; c < HID; c++) {
            __nv_bfloat16 h, l; bsplit(qbuf[c], h, l);
            qh[t * LDQ + c] = h; ql[t * LDQ + c] = l;
        }
    } else {
        __syncthreads();
    }
    __syncthreads();

    // ---- y GEMM: y[pos][64] = q[pos][128] @ M[128][64] -> ys col-major [o][pos] ----
    {
        wmma::fragment<wmma::accumulator, 16, 16, 16, float> acc[4];
#pragma unroll
        for (int nt = 0; nt < 4; nt++) wmma::fill_fragment(acc[nt], 0.f);
#pragma unroll
        for (int kt = 0; kt < 8; kt++) {
            wmma::fragment<wmma::matrix_a, 16, 16, 16, __nv_bfloat16, wmma::row_major> fAh, fAl;
            wmma::load_matrix_sync(fAh, qh + wid * 16 * LDQ + kt * 16, LDQ);
            wmma::load_matrix_sync(fAl, ql + wid * 16 * LDQ + kt * 16, LDQ);
#pragma unroll
            for (int nt = 0; nt < 4; nt++) {
                wmma::fragment<wmma::matrix_b, 16, 16, 16, __nv_bfloat16, wmma::row_major> fBh, fBl;
                wmma::load_matrix_sync(fBh, mh + (size_t)(kt * 16) * 64 + nt * 16, 64);
                wmma::load_matrix_sync(fBl, ml + (size_t)(kt * 16) * 64 + nt * 16, 64);
                wmma::mma_sync(acc[nt], fAh, fBh, acc[nt]);
                wmma::mma_sync(acc[nt], fAh, fBl, acc[nt]);
                wmma::mma_sync(acc[nt], fAl, fBh, acc[nt]);
            }
        }
        __syncthreads();                 // q-tile reads done before ys overlays ekq
#pragma unroll
        for (int nt = 0; nt < 4; nt++)
            wmma::store_matrix_sync(ys + nt * 16 * 132 + wid * 16, acc[nt], 132, wmma::mem_col_major);
    }
    __syncthreads();

    // ---- LN2 + store ----
    if (t < 128) {
        float y[64];
        float s = 0.f, s2 = 0.f;
#pragma unroll
        for (int o = 0; o < 64; o++) {
            float v = ys[o * 132 + t] + bos[o];
            y[o] = v; s += v; s2 += v * v;
        }
        float mn = s * (1.f / 64.f);
        float rs = rsqrtf(s2 * (1.f / 64.f) - mn * mn + 1e-5f);
        float* ob = out + (size_t)bb * CC * NPOS + pos0 + t;
#pragma unroll
        for (int o = 0; o < 64; o++)
            ob[(size_t)o * NPOS] = (y[o] - mn) * rs * g2s[o] + b2s[o];
    }
}

// ---------------- launch ----------------
extern "C" void kernel_launch(void* const* d_in, const int* in_sizes, int n_in,
                              void* d_out, int out_size) {
    (void)in_sizes; (void)n_in; (void)out_size;
    const float* x    = (const float*)d_in[0];
    const float* g1   = (const float*)d_in[1];
    const float* b1   = (const float*)d_in[2];
    const float* wqkv = (const float*)d_in[3];
    const float* wout = (const float*)d_in[4];
    const float* bout = (const float*)d_in[5];
    const float* g2   = (const float*)d_in[6];
    const float* b2   = (const float*)d_in[7];
    float* y = (float*)d_out;

    cudaFuncSetAttribute(la_pass1_kernel, cudaFuncAttributeMaxDynamicSharedMemorySize, P1_BYTES);
    cudaFuncSetAttribute(la_pass2_kernel, cudaFuncAttributeMaxDynamicSharedMemorySize, P2_BYTES);

    la_zero_kernel<<<33, 256>>>();
    la_pass1_kernel<<<dim3(NPOS / POSB, BB), TPB, P1_BYTES>>>(x, g1, b1, wqkv);
    la_fold_kernel<<<BB, 256>>>(wout);
    la_pass2_kernel<<<dim3(NPOS / POSB, BB), TPB, P2_BYTES>>>(x, g1, b1, wqkv, bout, g2, b2, y);
}

// round 14
// speedup vs baseline: 1.9199x; 1.9199x over previous
#include <cuda_runtime.h>
#include <cuda_bf16.h>
#include <mma.h>
#include <cstdint>

using namespace nvcuda;

#define BB    2
#define CC    64
#define NPOS  131072
#define HEADS 4
#define DHEAD 32
#define HID   128
#define TPB   256
#define POSB  128
#define LDX   72      // bf16 tile ld: 144B rows -> conflict-free LDSM
#define LDQ   40      // q tile ld: 80B rows -> conflict-free

typedef unsigned long long u64;
typedef unsigned int       u32;

// ---------------- device scratch ----------------
__device__ float g_ctx[BB * HEADS * DHEAD * DHEAD];
__device__ float g_Z[BB * HEADS * DHEAD];
__device__ __nv_bfloat16 g_Mh[BB][HID * CC];   // M split hi, [i][o] row-major
__device__ __nv_bfloat16 g_Ml[BB][HID * CC];   // M split lo

// ---------------- f32x2 helpers (stage B) ----------------
__device__ __forceinline__ u64 ffma2(u64 a, u64 b, u64 c) {
    u64 d; asm("fma.rn.f32x2 %0, %1, %2, %3;" : "=l"(d) : "l"(a), "l"(b), "l"(c)); return d;
}
__device__ __forceinline__ u64 fadd2(u64 a, u64 b) {
    u64 d; asm("add.rn.f32x2 %0, %1, %2;" : "=l"(d) : "l"(a), "l"(b)); return d;
}
__device__ __forceinline__ float hsum2(u64 a) {
    float lo, hi; asm("mov.b64 {%0,%1}, %2;" : "=f"(lo), "=f"(hi) : "l"(a)); return lo + hi;
}

// ---------------- kernel 0: zero accumulators ----------------
__global__ void la_zero_kernel() {
    int i = blockIdx.x * blockDim.x + threadIdx.x;
    if (i < BB * HEADS * DHEAD * DHEAD) g_ctx[i] = 0.f;
    if (i < BB * HEADS * DHEAD)         g_Z[i]   = 0.f;
}

// stage B: ctx[d][e] += sum_pos ek[d][pos]*vv[e][pos]; Z[d] += sum ek. 256 threads.
__device__ __forceinline__ void stageB(const float* ek, const float* vv, int bb, int h, int t) {
    const int d_own = t >> 3, e0 = t & 7;
    u64 a0 = 0, a1 = 0, a2 = 0, a3 = 0, za = 0;
    const float* ekr = ek + d_own * 132;
#pragma unroll 4
    for (int tt = 0; tt < POSB; tt += 4) {
        ulonglong2 ap  = *(const ulonglong2*)(ekr + tt);
        ulonglong2 bv0 = *(const ulonglong2*)(vv + (e0     ) * 132 + tt);
        ulonglong2 bv1 = *(const ulonglong2*)(vv + (e0 +  8) * 132 + tt);
        ulonglong2 bv2 = *(const ulonglong2*)(vv + (e0 + 16) * 132 + tt);
        ulonglong2 bv3 = *(const ulonglong2*)(vv + (e0 + 24) * 132 + tt);
        a0 = ffma2(ap.x, bv0.x, a0); a0 = ffma2(ap.y, bv0.y, a0);
        a1 = ffma2(ap.x, bv1.x, a1); a1 = ffma2(ap.y, bv1.y, a1);
        a2 = ffma2(ap.x, bv2.x, a2); a2 = ffma2(ap.y, bv2.y, a2);
        a3 = ffma2(ap.x, bv3.x, a3); a3 = ffma2(ap.y, bv3.y, a3);
        if (e0 == 0) za = fadd2(za, fadd2(ap.x, ap.y));
    }
    float* cb = g_ctx + (size_t)((bb * HEADS + h) * DHEAD + d_own) * DHEAD;
    atomicAdd(cb + e0,      hsum2(a0));
    atomicAdd(cb + e0 +  8, hsum2(a1));
    atomicAdd(cb + e0 + 16, hsum2(a2));
    atomicAdd(cb + e0 + 24, hsum2(a3));
    if (e0 == 0) atomicAdd(g_Z + (bb * HEADS + h) * DHEAD + d_own, hsum2(za));
}

__device__ __forceinline__ void bsplit(float v, __nv_bfloat16& h, __nv_bfloat16& l) {
    h = __float2bfloat16_rn(v);
    l = __float2bfloat16_rn(v - __bfloat162float(h));
}

// full-thread LN into split-bf16 A tiles (2 threads per position), scratch = 512 floats
__device__ __forceinline__ void ln_to_tiles(const float* __restrict__ x, int bb, int pos0, int t,
                                            __nv_bfloat16* xh, __nv_bfloat16* xl,
                                            float* scratch, const float* g1s, const float* b1s) {
    const int p = t & 127, half = t >> 7;
    const float* xb = x + (size_t)bb * CC * NPOS + pos0 + p;
    float xr[32];
    float s = 0.f, s2 = 0.f;
#pragma unroll
    for (int c = 0; c < 32; c++) {
        float v = __ldg(xb + (size_t)(half * 32 + c) * NPOS);
        xr[c] = v; s += v; s2 += v * v;
    }
    scratch[half * 128 + p]       = s;
    scratch[256 + half * 128 + p] = s2;
    __syncthreads();
    float st  = scratch[p] + scratch[128 + p];
    float st2 = scratch[256 + p] + scratch[384 + p];
    float mean = st * (1.f / 64.f);
    float rstd = rsqrtf(st2 * (1.f / 64.f) - mean * mean + 1e-5f);
#pragma unroll
    for (int c = 0; c < 32; c++) {
        int ch = half * 32 + c;
        float v = (xr[c] - mean) * rstd * g1s[ch] + b1s[ch];
        __nv_bfloat16 h, l; bsplit(v, h, l);
        xh[p * LDX + ch] = h; xl[p * LDX + ch] = l;
    }
}

// ================= pass1: LN + wmma [K;V] per-head GEMM + ctx/Z =================
#define P1_XH 0                      // 128*72*2 = 18432
#define P1_XL 18432
#define P1_WH 36864                  // 64*72*2 = 9216 (K rows 0-31, V rows 32-63)
#define P1_WL 46080
#define P1_EK 55296                  // 32*132*4 = 16896 (also LN scratch)
#define P1_VV 72192
#define P1_G1 89088
#define P1_B1 89344
#define P1_BYTES 89600

__global__ __launch_bounds__(TPB, 2)
void la_pass1_kernel(const float* __restrict__ x, const float* __restrict__ g1,
                     const float* __restrict__ b1, const float* __restrict__ wqkv) {
    extern __shared__ char smem[];
    __nv_bfloat16* xh = (__nv_bfloat16*)(smem + P1_XH);
    __nv_bfloat16* xl = (__nv_bfloat16*)(smem + P1_XL);
    __nv_bfloat16* wh = (__nv_bfloat16*)(smem + P1_WH);
    __nv_bfloat16* wl = (__nv_bfloat16*)(smem + P1_WL);
    float* ekf = (float*)(smem + P1_EK);
    float* vvf = (float*)(smem + P1_VV);
    float* g1s = (float*)(smem + P1_G1);
    float* b1s = (float*)(smem + P1_B1);

    const int t   = threadIdx.x;
    const int wid = t >> 5;
    const int bb   = blockIdx.y;
    const int pos0 = blockIdx.x * POSB;

    if (t < 64) { g1s[t] = g1[t]; b1s[t] = b1[t]; }
    ln_to_tiles(x, bb, pos0, t, xh, xl, ekf, g1s, b1s);
    __syncthreads();

    // hoist A fragments (x tiles; invariant across heads)
    wmma::fragment<wmma::matrix_a, 16, 16, 16, __nv_bfloat16, wmma::row_major> fAh[4], fAl[4];
#pragma unroll
    for (int kt = 0; kt < 4; kt++) {
        wmma::load_matrix_sync(fAh[kt], xh + wid * 16 * LDX + kt * 16, LDX);
        wmma::load_matrix_sync(fAl[kt], xl + wid * 16 * LDX + kt * 16, LDX);
    }

    for (int h = 0; h < HEADS; h++) {
        // stage K_h (rows 0-31) + V_h (rows 32-63), split bf16, ld 72
#pragma unroll
        for (int i = 0; i < 8; i++) {
            int idx = t + i * 256;        // pair index 0..2047
            int row = idx >> 5, kp = idx & 31;
            int srow = (row < 32) ? (128 + h * 32 + row) : (256 + h * 32 + (row - 32));
            float2 wv = *(const float2*)(wqkv + (size_t)srow * 64 + 2 * kp);
            __nv_bfloat16 h0, l0, h1, l1;
            bsplit(wv.x, h0, l0); bsplit(wv.y, h1, l1);
            wh[row * LDX + 2 * kp] = h0; wh[row * LDX + 2 * kp + 1] = h1;
            wl[row * LDX + 2 * kp] = l0; wl[row * LDX + 2 * kp + 1] = l1;
        }
        __syncthreads();

        wmma::fragment<wmma::accumulator, 16, 16, 16, float> accK[2], accV[2];
#pragma unroll
        for (int nt = 0; nt < 2; nt++) { wmma::fill_fragment(accK[nt], 0.f); wmma::fill_fragment(accV[nt], 0.f); }
#pragma unroll
        for (int kt = 0; kt < 4; kt++) {
#pragma unroll
            for (int nt = 0; nt < 2; nt++) {
                wmma::fragment<wmma::matrix_b, 16, 16, 16, __nv_bfloat16, wmma::col_major> fBh, fBl;
                wmma::load_matrix_sync(fBh, wh + (nt * 16) * LDX + kt * 16, LDX);
                wmma::load_matrix_sync(fBl, wl + (nt * 16) * LDX + kt * 16, LDX);
                wmma::mma_sync(accK[nt], fAh[kt], fBh, accK[nt]);
                wmma::mma_sync(accK[nt], fAh[kt], fBl, accK[nt]);
                wmma::mma_sync(accK[nt], fAl[kt], fBh, accK[nt]);
                wmma::load_matrix_sync(fBh, wh + (32 + nt * 16) * LDX + kt * 16, LDX);
                wmma::load_matrix_sync(fBl, wl + (32 + nt * 16) * LDX + kt * 16, LDX);
                wmma::mma_sync(accV[nt], fAh[kt], fBh, accV[nt]);
                wmma::mma_sync(accV[nt], fAh[kt], fBl, accV[nt]);
                wmma::mma_sync(accV[nt], fAl[kt], fBh, accV[nt]);
            }
        }
#pragma unroll
        for (int nt = 0; nt < 2; nt++) {
            wmma::store_matrix_sync(ekf + nt * 16 * 132 + wid * 16, accK[nt], 132, wmma::mem_col_major);
            wmma::store_matrix_sync(vvf + nt * 16 * 132 + wid * 16, accV[nt], 132, wmma::mem_col_major);
        }
        __syncthreads();
#pragma unroll
        for (int j = 0; j < 16; j++) {
            int idx = t + j * 256;
            int row = idx >> 7, p = idx & 127;
            ekf[row * 132 + p] = __expf(ekf[row * 132 + p]);
        }
        __syncthreads();
        stageB(ekf, vvf, bb, h, t);
        __syncthreads();
    }
}

// ---------------- kernel 2: fold -> split-bf16 M [i][o] ----------------
__global__ void la_fold_kernel(const float* __restrict__ wout) {
    int bb = blockIdx.x;
    for (int idx = threadIdx.x; idx < HID * CC; idx += blockDim.x) {
        int i = idx >> 6, o = idx & 63;
        int h = i >> 5,   d = i & 31;
        const float* cp = g_ctx + (size_t)((bb * HEADS + h) * DHEAD + d) * DHEAD;
        const float* wp = wout + (size_t)o * HID + h * DHEAD;
        float acc = 0.f;
#pragma unroll
        for (int e = 0; e < 32; e++) acc += wp[e] * cp[e];
        float m = acc / g_Z[(bb * HEADS + h) * DHEAD + d];
        __nv_bfloat16 mh, ml; bsplit(m, mh, ml);
        g_Mh[bb][i * 64 + o] = mh;
        g_Ml[bb][i * 64 + o] = ml;
    }
}

// ===== pass2: LN + per-head (Q GEMM + softmax + y+=q@M) + LN2; q stays on-chip =====
#define P2_XH  0
#define P2_XL  18432
#define P2_WQH 36864      // 32*72*2 = 4608
#define P2_WQL 41472
#define P2_MH  46080      // 4608
#define P2_ML  50688
#define P2_EK  55296      // 32*132*4 = 16896 (also LN scratch)
#define P2_QH  72192      // 128*40*2 = 10240
#define P2_QL  82432
#define P2_PAR 92672      // 5*64 floats
#define P2_BYTES 93952
#define P2_YS  55296      // 64*132*4 = 33792, overlays EK/QH after heads done

__global__ __launch_bounds__(TPB, 2)
void la_pass2_kernel(const float* __restrict__ x, const float* __restrict__ g1,
                     const float* __restrict__ b1, const float* __restrict__ wqkv,
                     const float* __restrict__ bout, const float* __restrict__ g2,
                     const float* __restrict__ b2, float* __restrict__ out) {
    extern __shared__ char smem[];
    __nv_bfloat16* xh  = (__nv_bfloat16*)(smem + P2_XH);
    __nv_bfloat16* xl  = (__nv_bfloat16*)(smem + P2_XL);
    __nv_bfloat16* wqh = (__nv_bfloat16*)(smem + P2_WQH);
    __nv_bfloat16* wql = (__nv_bfloat16*)(smem + P2_WQL);
    __nv_bfloat16* mh  = (__nv_bfloat16*)(smem + P2_MH);
    __nv_bfloat16* ml  = (__nv_bfloat16*)(smem + P2_ML);
    __nv_bfloat16* qh  = (__nv_bfloat16*)(smem + P2_QH);
    __nv_bfloat16* ql  = (__nv_bfloat16*)(smem + P2_QL);
    float* ekf = (float*)(smem + P2_EK);
    float* ys  = (float*)(smem + P2_YS);
    float* g1s = (float*)(smem + P2_PAR);
    float* b1s = g1s + 64;
    float* g2s = b1s + 64;
    float* b2s = g2s + 64;
    float* bos = b2s + 64;

    const int t   = threadIdx.x;
    const int wid = t >> 5;
    const int bb   = blockIdx.y;
    const int pos0 = blockIdx.x * POSB;

    if (t < 64) {
        g1s[t] = g1[t]; b1s[t] = b1[t];
        g2s[t] = g2[t]; b2s[t] = b2[t]; bos[t] = bout[t];
    }
    ln_to_tiles(x, bb, pos0, t, xh, xl, ekf, g1s, b1s);
    __syncthreads();

    // persistent y accumulators: warp -> pos rows wid*16; nt -> o cols nt*16
    wmma::fragment<wmma::accumulator, 16, 16, 16, float> acc_y[4];
#pragma unroll
    for (int nt = 0; nt < 4; nt++) wmma::fill_fragment(acc_y[nt], 0.f);

    for (int h = 0; h < HEADS; h++) {
        // stage WQ_h (32x64 split, ld 72) and M_h (32x64, already split in global)
#pragma unroll
        for (int i = 0; i < 4; i++) {
            int idx = t + i * 256;        // pair index 0..1023
            int r = idx >> 5, kp = idx & 31;
            float2 wv = *(const float2*)(wqkv + (size_t)(h * 32 + r) * 64 + 2 * kp);
            __nv_bfloat16 h0, l0, h1, l1;
            bsplit(wv.x, h0, l0); bsplit(wv.y, h1, l1);
            wqh[r * LDX + 2 * kp] = h0; wqh[r * LDX + 2 * kp + 1] = h1;
            wql[r * LDX + 2 * kp] = l0; wql[r * LDX + 2 * kp + 1] = l1;
        }
#pragma unroll
        for (int i = 0; i < 4; i++) {
            int idx = t + i * 256;        // u32 index 0..1023 (2 bf16 each)
            int k = idx >> 5, op = idx & 31;
            *(u32*)(mh + k * LDX + 2 * op) = *(const u32*)(g_Mh[bb] + (size_t)(h * 32 + k) * 64 + 2 * op);
            *(u32*)(ml + k * LDX + 2 * op) = *(const u32*)(g_Ml[bb] + (size_t)(h * 32 + k) * 64 + 2 * op);
        }
        __syncthreads();

        // Q GEMM: logits[32 qrows][128 pos]
        {
            wmma::fragment<wmma::accumulator, 16, 16, 16, float> acc[2];
            wmma::fill_fragment(acc[0], 0.f); wmma::fill_fragment(acc[1], 0.f);
#pragma unroll
            for (int kt = 0; kt < 4; kt++) {
                wmma::fragment<wmma::matrix_a, 16, 16, 16, __nv_bfloat16, wmma::row_major> fAh, fAl;
                wmma::load_matrix_sync(fAh, xh + wid * 16 * LDX + kt * 16, LDX);
                wmma::load_matrix_sync(fAl, xl + wid * 16 * LDX + kt * 16, LDX);
#pragma unroll
                for (int nt = 0; nt < 2; nt++) {
                    wmma::fragment<wmma::matrix_b, 16, 16, 16, __nv_bfloat16, wmma::col_major> fBh, fBl;
                    wmma::load_matrix_sync(fBh, wqh + (nt * 16) * LDX + kt * 16, LDX);
                    wmma::load_matrix_sync(fBl, wql + (nt * 16) * LDX + kt * 16, LDX);
                    wmma::mma_sync(acc[nt], fAh, fBh, acc[nt]);
                    wmma::mma_sync(acc[nt], fAh, fBl, acc[nt]);
                    wmma::mma_sync(acc[nt], fAl, fBh, acc[nt]);
                }
            }
            wmma::store_matrix_sync(ekf + wid * 16,            acc[0], 132, wmma::mem_col_major);
            wmma::store_matrix_sync(ekf + 16 * 132 + wid * 16, acc[1], 132, wmma::mem_col_major);
        }
        __syncthreads();

        // softmax per position -> q tiles (ld 40)
        if (t < 128) {
            float qv[32];
            float mx = -1e30f;
#pragma unroll
            for (int d = 0; d < 32; d++) { qv[d] = ekf[d * 132 + t]; mx = fmaxf(mx, qv[d]); }
            float ss = 0.f;
#pragma unroll
            for (int d = 0; d < 32; d++) { qv[d] = __expf(qv[d] - mx); ss += qv[d]; }
            float sc = 0.17677669529663687f / ss;
#pragma unroll
            for (int d = 0; d < 32; d++) {
                __nv_bfloat16 hv, lv; bsplit(qv[d] * sc, hv, lv);
                qh[t * LDQ + d] = hv; ql[t * LDQ + d] = lv;
            }
        }
        __syncthreads();

        // y += q_h @ M_h  (A: q [128x32] ld 40; B: M row-major [32x64] ld 72)
#pragma unroll
        for (int kt = 0; kt < 2; kt++) {
            wmma::fragment<wmma::matrix_a, 16, 16, 16, __nv_bfloat16, wmma::row_major> fAh, fAl;
            wmma::load_matrix_sync(fAh, qh + wid * 16 * LDQ + kt * 16, LDQ);
            wmma::load_matrix_sync(fAl, ql + wid * 16 * LDQ + kt * 16, LDQ);
#pragma unroll
            for (int nt = 0; nt < 4; nt++) {
                wmma::fragment<wmma::matrix_b, 16, 16, 16, __nv_bfloat16, wmma::row_major> fBh, fBl;
                wmma::load_matrix_sync(fBh, mh + (kt * 16) * LDX + nt * 16, LDX);
                wmma::load_matrix_sync(fBl, ml + (kt * 16) * LDX + nt * 16, LDX);
                wmma::mma_sync(acc_y[nt], fAh, fBh, acc_y[nt]);
                wmma::mma_sync(acc_y[nt], fAh, fBl, acc_y[nt]);
                wmma::mma_sync(acc_y[nt], fAl, fBh, acc_y[nt]);
            }
        }
        __syncthreads();
    }

    // store y col-major [o][pos] (overlays dead ek/q buffers)
#pragma unroll
    for (int nt = 0; nt < 4; nt++)
        wmma::store_matrix_sync(ys + nt * 16 * 132 + wid * 16, acc_y[nt], 132, wmma::mem_col_major);
    __syncthreads();

    // LN2 + store
    if (t < 128) {
        float y[64];
        float s = 0.f, s2 = 0.f;
#pragma unroll
        for (int o = 0; o < 64; o++) {
            float v = ys[o * 132 + t] + bos[o];
            y[o] = v; s += v; s2 += v * v;
        }
        float mn = s * (1.f / 64.f);
        float rs = rsqrtf(s2 * (1.f / 64.f) - mn * mn + 1e-5f);
        float* ob = out + (size_t)bb * CC * NPOS + pos0 + t;
#pragma unroll
        for (int o = 0; o < 64; o++)
            ob[(size_t)o * NPOS] = (y[o] - mn) * rs * g2s[o] + b2s[o];
    }
}

// ---------------- launch ----------------
extern "C" void kernel_launch(void* const* d_in, const int* in_sizes, int n_in,
                              void* d_out, int out_size) {
    (void)in_sizes; (void)n_in; (void)out_size;
    const float* x    = (const float*)d_in[0];
    const float* g1   = (const float*)d_in[1];
    const float* b1   = (const float*)d_in[2];
    const float* wqkv = (const float*)d_in[3];
    const float* wout = (const float*)d_in[4];
    const float* bout = (const float*)d_in[5];
    const float* g2   = (const float*)d_in[6];
    const float* b2   = (const float*)d_in[7];
    float* y = (float*)d_out;

    cudaFuncSetAttribute(la_pass1_kernel, cudaFuncAttributeMaxDynamicSharedMemorySize, P1_BYTES);
    cudaFuncSetAttribute(la_pass2_kernel, cudaFuncAttributeMaxDynamicSharedMemorySize, P2_BYTES);

    la_zero_kernel<<<33, 256>>>();
    la_pass1_kernel<<<dim3(NPOS / POSB, BB), TPB, P1_BYTES>>>(x, g1, b1, wqkv);
    la_fold_kernel<<<BB, 256>>>(wout);
    la_pass2_kernel<<<dim3(NPOS / POSB, BB), TPB, P2_BYTES>>>(x, g1, b1, wqkv, bout, g2, b2, y);
}

// round 15
// speedup vs baseline: 2.1440x; 1.1167x over previous
#include <cuda_runtime.h>
#include <cuda_bf16.h>
#include <mma.h>
#include <cstdint>

using namespace nvcuda;

#define BB    2
#define CC    64
#define NPOS  131072
#define HEADS 4
#define DHEAD 32
#define HID   128
#define TPB   256
#define POSB  128
#define LDX   72      // bf16 tile ld: 144B rows -> conflict-free LDSM
#define LDQ   40      // q tile ld: 80B rows -> conflict-free
#define LDE   136     // ek/vv bf16 tile ld: 272B rows -> conflict-free

typedef unsigned long long u64;
typedef unsigned int       u32;

// ---------------- device scratch ----------------
__device__ float g_ctx[BB * HEADS * DHEAD * DHEAD];
__device__ float g_Z[BB * HEADS * DHEAD];
__device__ __nv_bfloat16 g_Mh[BB][HID * CC];   // M split hi, [i][o] row-major
__device__ __nv_bfloat16 g_Ml[BB][HID * CC];   // M split lo

// ---------------- kernel 0: zero accumulators ----------------
__global__ void la_zero_kernel() {
    int i = blockIdx.x * blockDim.x + threadIdx.x;
    if (i < BB * HEADS * DHEAD * DHEAD) g_ctx[i] = 0.f;
    if (i < BB * HEADS * DHEAD)         g_Z[i]   = 0.f;
}

__device__ __forceinline__ void bsplit(float v, __nv_bfloat16& h, __nv_bfloat16& l) {
    h = __float2bfloat16_rn(v);
    l = __float2bfloat16_rn(v - __bfloat162float(h));
}

// full-thread LN into split-bf16 A tiles (2 threads per position), scratch = 512 floats
__device__ __forceinline__ void ln_to_tiles(const float* __restrict__ x, int bb, int pos0, int t,
                                            __nv_bfloat16* xh, __nv_bfloat16* xl,
                                            float* scratch, const float* g1s, const float* b1s) {
    const int p = t & 127, half = t >> 7;
    const float* xb = x + (size_t)bb * CC * NPOS + pos0 + p;
    float xr[32];
    float s = 0.f, s2 = 0.f;
#pragma unroll
    for (int c = 0; c < 32; c++) {
        float v = __ldg(xb + (size_t)(half * 32 + c) * NPOS);
        xr[c] = v; s += v; s2 += v * v;
    }
    scratch[half * 128 + p]       = s;
    scratch[256 + half * 128 + p] = s2;
    __syncthreads();
    float st  = scratch[p] + scratch[128 + p];
    float st2 = scratch[256 + p] + scratch[384 + p];
    float mean = st * (1.f / 64.f);
    float rstd = rsqrtf(st2 * (1.f / 64.f) - mean * mean + 1e-5f);
#pragma unroll
    for (int c = 0; c < 32; c++) {
        int ch = half * 32 + c;
        float v = (xr[c] - mean) * rstd * g1s[ch] + b1s[ch];
        __nv_bfloat16 h, l; bsplit(v, h, l);
        xh[p * LDX + ch] = h; xl[p * LDX + ch] = l;
    }
}

// ================= pass1: LN + wmma K/V GEMM + wmma ctx GEMM + Z =================
#define P1_XH  0                     // 128*72*2 = 18432
#define P1_XL  18432
#define P1_WH  36864                 // 64*72*2 = 9216 (K rows 0-31, V rows 32-63)
#define P1_WL  46080
#define P1_EKF 55296                 // fp32 32x132 = 16896 (also LN scratch)
#define P1_VVF 72192                 // fp32 32x132
// bf16 overlay of the fp32 region (written after regs are loaded + sync):
#define P1_EKH 55296                 // 32*136*2 = 8704
#define P1_EKL 64000
#define P1_VVH 72704
#define P1_VVL 81408                 // ends 90112
#define P1_CB  90112                 // 8 warp ctx bufs 16x20 fp32 = 10240
#define P1_G1  100352
#define P1_B1  100608
#define P1_BYTES 100864

__global__ __launch_bounds__(TPB, 2)
void la_pass1_kernel(const float* __restrict__ x, const float* __restrict__ g1,
                     const float* __restrict__ b1, const float* __restrict__ wqkv) {
    extern __shared__ char smem[];
    __nv_bfloat16* xh  = (__nv_bfloat16*)(smem + P1_XH);
    __nv_bfloat16* xl  = (__nv_bfloat16*)(smem + P1_XL);
    __nv_bfloat16* wh  = (__nv_bfloat16*)(smem + P1_WH);
    __nv_bfloat16* wl  = (__nv_bfloat16*)(smem + P1_WL);
    float* ekf = (float*)(smem + P1_EKF);
    float* vvf = (float*)(smem + P1_VVF);
    __nv_bfloat16* ekh = (__nv_bfloat16*)(smem + P1_EKH);
    __nv_bfloat16* ekl = (__nv_bfloat16*)(smem + P1_EKL);
    __nv_bfloat16* vvh = (__nv_bfloat16*)(smem + P1_VVH);
    __nv_bfloat16* vvl = (__nv_bfloat16*)(smem + P1_VVL);
    float* cb  = (float*)(smem + P1_CB);
    float* g1s = (float*)(smem + P1_G1);
    float* b1s = (float*)(smem + P1_B1);

    const int t   = threadIdx.x;
    const int wid = t >> 5;
    const int bb   = blockIdx.y;
    const int pos0 = blockIdx.x * POSB;

    if (t < 64) { g1s[t] = g1[t]; b1s[t] = b1[t]; }
    ln_to_tiles(x, bb, pos0, t, xh, xl, ekf, g1s, b1s);
    __syncthreads();

    // hoist x A fragments (invariant across heads)
    wmma::fragment<wmma::matrix_a, 16, 16, 16, __nv_bfloat16, wmma::row_major> fAh[4], fAl[4];
#pragma unroll
    for (int kt = 0; kt < 4; kt++) {
        wmma::load_matrix_sync(fAh[kt], xh + wid * 16 * LDX + kt * 16, LDX);
        wmma::load_matrix_sync(fAl[kt], xl + wid * 16 * LDX + kt * 16, LDX);
    }

    // split-pass ownership: row d = t>>3, positions pl..pl+15
    const int sd = t >> 3, pl = (t & 7) * 16;
    // ctx GEMM ownership: warp -> (kh, mt, nt)
    const int kh = wid >> 2, mt = (wid >> 1) & 1, ctn = wid & 1;

    for (int h = 0; h < HEADS; h++) {
        // ---- stage K_h/V_h split-bf16 (ld 72) ----
#pragma unroll
        for (int i = 0; i < 8; i++) {
            int idx = t + i * 256;        // pair index 0..2047
            int row = idx >> 5, kp = idx & 31;
            int srow = (row < 32) ? (128 + h * 32 + row) : (256 + h * 32 + (row - 32));
            float2 wv = *(const float2*)(wqkv + (size_t)srow * 64 + 2 * kp);
            __nv_bfloat16 h0, l0, h1, l1;
            bsplit(wv.x, h0, l0); bsplit(wv.y, h1, l1);
            wh[row * LDX + 2 * kp] = h0; wh[row * LDX + 2 * kp + 1] = h1;
            wl[row * LDX + 2 * kp] = l0; wl[row * LDX + 2 * kp + 1] = l1;
        }
        __syncthreads();

        // ---- K/V GEMM; exp applied elementwise in the K fragments ----
        {
            wmma::fragment<wmma::accumulator, 16, 16, 16, float> accK[2], accV[2];
#pragma unroll
            for (int nt = 0; nt < 2; nt++) { wmma::fill_fragment(accK[nt], 0.f); wmma::fill_fragment(accV[nt], 0.f); }
#pragma unroll
            for (int kt = 0; kt < 4; kt++) {
#pragma unroll
                for (int nt = 0; nt < 2; nt++) {
                    wmma::fragment<wmma::matrix_b, 16, 16, 16, __nv_bfloat16, wmma::col_major> fBh, fBl;
                    wmma::load_matrix_sync(fBh, wh + (nt * 16) * LDX + kt * 16, LDX);
                    wmma::load_matrix_sync(fBl, wl + (nt * 16) * LDX + kt * 16, LDX);
                    wmma::mma_sync(accK[nt], fAh[kt], fBh, accK[nt]);
                    wmma::mma_sync(accK[nt], fAh[kt], fBl, accK[nt]);
                    wmma::mma_sync(accK[nt], fAl[kt], fBh, accK[nt]);
                    wmma::load_matrix_sync(fBh, wh + (32 + nt * 16) * LDX + kt * 16, LDX);
                    wmma::load_matrix_sync(fBl, wl + (32 + nt * 16) * LDX + kt * 16, LDX);
                    wmma::mma_sync(accV[nt], fAh[kt], fBh, accV[nt]);
                    wmma::mma_sync(accV[nt], fAh[kt], fBl, accV[nt]);
                    wmma::mma_sync(accV[nt], fAl[kt], fBh, accV[nt]);
                }
            }
#pragma unroll
            for (int nt = 0; nt < 2; nt++) {
#pragma unroll
                for (int e = 0; e < accK[nt].num_elements; e++)
                    accK[nt].x[e] = __expf(accK[nt].x[e]);
                // [d][pos] fp32, ld 132
                wmma::store_matrix_sync(ekf + nt * 16 * 132 + wid * 16, accK[nt], 132, wmma::mem_col_major);
                wmma::store_matrix_sync(vvf + nt * 16 * 132 + wid * 16, accV[nt], 132, wmma::mem_col_major);
            }
        }
        __syncthreads();

        // ---- split pass: fp32 -> bf16 hi/lo tiles (in-place overlay) + Z ----
        {
            float er[16], vr[16];
#pragma unroll
            for (int j = 0; j < 4; j++) {
                *(float4*)(er + 4 * j) = *(const float4*)(ekf + sd * 132 + pl + 4 * j);
                *(float4*)(vr + 4 * j) = *(const float4*)(vvf + sd * 132 + pl + 4 * j);
            }
            float zs = 0.f;
#pragma unroll
            for (int j = 0; j < 16; j++) zs += er[j];
            zs += __shfl_xor_sync(0xffffffffu, zs, 1);
            zs += __shfl_xor_sync(0xffffffffu, zs, 2);
            zs += __shfl_xor_sync(0xffffffffu, zs, 4);
            __syncthreads();            // fp32 reads complete before bf16 overlay
#pragma unroll
            for (int j = 0; j < 8; j++) {
                __nv_bfloat16 h0, l0, h1, l1;
                bsplit(er[2 * j], h0, l0); bsplit(er[2 * j + 1], h1, l1);
                *(u32*)(ekh + sd * LDE + pl + 2 * j) = (u32)__bfloat16_as_ushort(h0) | ((u32)__bfloat16_as_ushort(h1) << 16);
                *(u32*)(ekl + sd * LDE + pl + 2 * j) = (u32)__bfloat16_as_ushort(l0) | ((u32)__bfloat16_as_ushort(l1) << 16);
                bsplit(vr[2 * j], h0, l0); bsplit(vr[2 * j + 1], h1, l1);
                *(u32*)(vvh + sd * LDE + pl + 2 * j) = (u32)__bfloat16_as_ushort(h0) | ((u32)__bfloat16_as_ushort(h1) << 16);
                *(u32*)(vvl + sd * LDE + pl + 2 * j) = (u32)__bfloat16_as_ushort(l0) | ((u32)__bfloat16_as_ushort(l1) << 16);
            }
            if ((t & 7) == 0)
                atomicAdd(g_Z + (bb * HEADS + h) * DHEAD + sd, zs);
        }
        __syncthreads();

        // ---- ctx GEMM: ctx[d][e] += ek @ vv^T over k=pos, 3-way split ----
        {
            wmma::fragment<wmma::accumulator, 16, 16, 16, float> accC;
            wmma::fill_fragment(accC, 0.f);
#pragma unroll
            for (int kt = 0; kt < 4; kt++) {
                int k0 = kh * 64 + kt * 16;
                wmma::fragment<wmma::matrix_a, 16, 16, 16, __nv_bfloat16, wmma::row_major> cAh, cAl;
                wmma::fragment<wmma::matrix_b, 16, 16, 16, __nv_bfloat16, wmma::col_major> cBh, cBl;
                wmma::load_matrix_sync(cAh, ekh + (mt * 16) * LDE + k0, LDE);
                wmma::load_matrix_sync(cAl, ekl + (mt * 16) * LDE + k0, LDE);
                wmma::load_matrix_sync(cBh, vvh + (ctn * 16) * LDE + k0, LDE);
                wmma::load_matrix_sync(cBl, vvl + (ctn * 16) * LDE + k0, LDE);
                wmma::mma_sync(accC, cAh, cBh, accC);
                wmma::mma_sync(accC, cAh, cBl, accC);
                wmma::mma_sync(accC, cAl, cBh, accC);
            }
            wmma::store_matrix_sync(cb + wid * 320, accC, 20, wmma::mem_row_major);
        }
        __syncthreads();

        // ---- reduce k-halves + atomicAdd ctx ----
#pragma unroll
        for (int j = 0; j < 4; j++) {
            int idx = t + j * 256;       // 0..1023
            int d = idx >> 5, e = idx & 31;
            int bi = (d >> 4) * 2 + (e >> 4);
            float v = cb[bi * 320 + (d & 15) * 20 + (e & 15)]
                    + cb[(4 + bi) * 320 + (d & 15) * 20 + (e & 15)];
            atomicAdd(g_ctx + (size_t)((bb * HEADS + h) * DHEAD + d) * DHEAD + e, v);
        }
        __syncthreads();
    }
}

// ---------------- kernel 2: fold -> split-bf16 M [i][o] ----------------
__global__ void la_fold_kernel(const float* __restrict__ wout) {
    int bb = blockIdx.x;
    for (int idx = threadIdx.x; idx < HID * CC; idx += blockDim.x) {
        int i = idx >> 6, o = idx & 63;
        int h = i >> 5,   d = i & 31;
        const float* cp = g_ctx + (size_t)((bb * HEADS + h) * DHEAD + d) * DHEAD;
        const float* wp = wout + (size_t)o * HID + h * DHEAD;
        float acc = 0.f;
#pragma unroll
        for (int e = 0; e < 32; e++) acc += wp[e] * cp[e];
        float m = acc / g_Z[(bb * HEADS + h) * DHEAD + d];
        __nv_bfloat16 mh, ml; bsplit(m, mh, ml);
        g_Mh[bb][i * 64 + o] = mh;
        g_Ml[bb][i * 64 + o] = ml;
    }
}

// ===== pass2: LN + per-head (Q GEMM + softmax + y+=q@M) + LN2; q stays on-chip =====
#define P2_XH  0
#define P2_XL  18432
#define P2_WQH 36864      // 32*72*2 = 4608
#define P2_WQL 41472
#define P2_MH  46080      // 4608
#define P2_ML  50688
#define P2_EK  55296      // 32*132*4 = 16896 (also LN scratch)
#define P2_QH  72192      // 128*40*2 = 10240
#define P2_QL  82432
#define P2_PAR 92672      // 5*64 floats
#define P2_BYTES 93952
#define P2_YS  55296      // 64*132*4 = 33792, overlays EK/QH after heads done

__global__ __launch_bounds__(TPB, 2)
void la_pass2_kernel(const float* __restrict__ x, const float* __restrict__ g1,
                     const float* __restrict__ b1, const float* __restrict__ wqkv,
                     const float* __restrict__ bout, const float* __restrict__ g2,
                     const float* __restrict__ b2, float* __restrict__ out) {
    extern __shared__ char smem[];
    __nv_bfloat16* xh  = (__nv_bfloat16*)(smem + P2_XH);
    __nv_bfloat16* xl  = (__nv_bfloat16*)(smem + P2_XL);
    __nv_bfloat16* wqh = (__nv_bfloat16*)(smem + P2_WQH);
    __nv_bfloat16* wql = (__nv_bfloat16*)(smem + P2_WQL);
    __nv_bfloat16* mh  = (__nv_bfloat16*)(smem + P2_MH);
    __nv_bfloat16* ml  = (__nv_bfloat16*)(smem + P2_ML);
    __nv_bfloat16* qh  = (__nv_bfloat16*)(smem + P2_QH);
    __nv_bfloat16* ql  = (__nv_bfloat16*)(smem + P2_QL);
    float* ekf = (float*)(smem + P2_EK);
    float* ys  = (float*)(smem + P2_YS);
    float* g1s = (float*)(smem + P2_PAR);
    float* b1s = g1s + 64;
    float* g2s = b1s + 64;
    float* b2s = g2s + 64;
    float* bos = b2s + 64;

    const int t   = threadIdx.x;
    const int wid = t >> 5;
    const int bb   = blockIdx.y;
    const int pos0 = blockIdx.x * POSB;

    if (t < 64) {
        g1s[t] = g1[t]; b1s[t] = b1[t];
        g2s[t] = g2[t]; b2s[t] = b2[t]; bos[t] = bout[t];
    }
    ln_to_tiles(x, bb, pos0, t, xh, xl, ekf, g1s, b1s);
    __syncthreads();

    wmma::fragment<wmma::accumulator, 16, 16, 16, float> acc_y[4];
#pragma unroll
    for (int nt = 0; nt < 4; nt++) wmma::fill_fragment(acc_y[nt], 0.f);

    for (int h = 0; h < HEADS; h++) {
#pragma unroll
        for (int i = 0; i < 4; i++) {
            int idx = t + i * 256;        // pair index 0..1023
            int r = idx >> 5, kp = idx & 31;
            float2 wv = *(const float2*)(wqkv + (size_t)(h * 32 + r) * 64 + 2 * kp);
            __nv_bfloat16 h0, l0, h1, l1;
            bsplit(wv.x, h0, l0); bsplit(wv.y, h1, l1);
            wqh[r * LDX + 2 * kp] = h0; wqh[r * LDX + 2 * kp + 1] = h1;
            wql[r * LDX + 2 * kp] = l0; wql[r * LDX + 2 * kp + 1] = l1;
        }
#pragma unroll
        for (int i = 0; i < 4; i++) {
            int idx = t + i * 256;        // u32 index 0..1023
            int k = idx >> 5, op = idx & 31;
            *(u32*)(mh + k * LDX + 2 * op) = *(const u32*)(g_Mh[bb] + (size_t)(h * 32 + k) * 64 + 2 * op);
            *(u32*)(ml + k * LDX + 2 * op) = *(const u32*)(g_Ml[bb] + (size_t)(h * 32 + k) * 64 + 2 * op);
        }
        __syncthreads();

        // Q GEMM: logits[32 qrows][128 pos]
        {
            wmma::fragment<wmma::accumulator, 16, 16, 16, float> acc[2];
            wmma::fill_fragment(acc[0], 0.f); wmma::fill_fragment(acc[1], 0.f);
#pragma unroll
            for (int kt = 0; kt < 4; kt++) {
                wmma::fragment<wmma::matrix_a, 16, 16, 16, __nv_bfloat16, wmma::row_major> fAh, fAl;
                wmma::load_matrix_sync(fAh, xh + wid * 16 * LDX + kt * 16, LDX);
                wmma::load_matrix_sync(fAl, xl + wid * 16 * LDX + kt * 16, LDX);
#pragma unroll
                for (int nt = 0; nt < 2; nt++) {
                    wmma::fragment<wmma::matrix_b, 16, 16, 16, __nv_bfloat16, wmma::col_major> fBh, fBl;
                    wmma::load_matrix_sync(fBh, wqh + (nt * 16) * LDX + kt * 16, LDX);
                    wmma::load_matrix_sync(fBl, wql + (nt * 16) * LDX + kt * 16, LDX);
                    wmma::mma_sync(acc[nt], fAh, fBh, acc[nt]);
                    wmma::mma_sync(acc[nt], fAh, fBl, acc[nt]);
                    wmma::mma_sync(acc[nt], fAl, fBh, acc[nt]);
                }
            }
            wmma::store_matrix_sync(ekf + wid * 16,            acc[0], 132, wmma::mem_col_major);
            wmma::store_matrix_sync(ekf + 16 * 132 + wid * 16, acc[1], 132, wmma::mem_col_major);
        }
        __syncthreads();

        // softmax per position -> q tiles (ld 40)
        if (t < 128) {
            float qv[32];
            float mx = -1e30f;
#pragma unroll
            for (int d = 0; d < 32; d++) { qv[d] = ekf[d * 132 + t]; mx = fmaxf(mx, qv[d]); }
            float ss = 0.f;
#pragma unroll
            for (int d = 0; d < 32; d++) { qv[d] = __expf(qv[d] - mx); ss += qv[d]; }
            float sc = 0.17677669529663687f / ss;
#pragma unroll
            for (int d = 0; d < 32; d++) {
                __nv_bfloat16 hv, lv; bsplit(qv[d] * sc, hv, lv);
                qh[t * LDQ + d] = hv; ql[t * LDQ + d] = lv;
            }
        }
        __syncthreads();

        // y += q_h @ M_h
#pragma unroll
        for (int kt = 0; kt < 2; kt++) {
            wmma::fragment<wmma::matrix_a, 16, 16, 16, __nv_bfloat16, wmma::row_major> fAh, fAl;
            wmma::load_matrix_sync(fAh, qh + wid * 16 * LDQ + kt * 16, LDQ);
            wmma::load_matrix_sync(fAl, ql + wid * 16 * LDQ + kt * 16, LDQ);
#pragma unroll
            for (int nt = 0; nt < 4; nt++) {
                wmma::fragment<wmma::matrix_b, 16, 16, 16, __nv_bfloat16, wmma::row_major> fBh, fBl;
                wmma::load_matrix_sync(fBh, mh + (kt * 16) * LDX + nt * 16, LDX);
                wmma::load_matrix_sync(fBl, ml + (kt * 16) * LDX + nt * 16, LDX);
                wmma::mma_sync(acc_y[nt], fAh, fBh, acc_y[nt]);
                wmma::mma_sync(acc_y[nt], fAh, fBl, acc_y[nt]);
                wmma::mma_sync(acc_y[nt], fAl, fBh, acc_y[nt]);
            }
        }
        __syncthreads();
    }

#pragma unroll
    for (int nt = 0; nt < 4; nt++)
        wmma::store_matrix_sync(ys + nt * 16 * 132 + wid * 16, acc_y[nt], 132, wmma::mem_col_major);
    __syncthreads();

    if (t < 128) {
        float y[64];
        float s = 0.f, s2 = 0.f;
#pragma unroll
        for (int o = 0; o < 64; o++) {
            float v = ys[o * 132 + t] + bos[o];
            y[o] = v; s += v; s2 += v * v;
        }
        float mn = s * (1.f / 64.f);
        float rs = rsqrtf(s2 * (1.f / 64.f) - mn * mn + 1e-5f);
        float* ob = out + (size_t)bb * CC * NPOS + pos0 + t;
#pragma unroll
        for (int o = 0; o < 64; o++)
            ob[(size_t)o * NPOS] = (y[o] - mn) * rs * g2s[o] + b2s[o];
    }
}

// ---------------- launch ----------------
extern "C" void kernel_launch(void* const* d_in, const int* in_sizes, int n_in,
                              void* d_out, int out_size) {
    (void)in_sizes; (void)n_in; (void)out_size;
    const float* x    = (const float*)d_in[0];
    const float* g1   = (const float*)d_in[1];
    const float* b1   = (const float*)d_in[2];
    const float* wqkv = (const float*)d_in[3];
    const float* wout = (const float*)d_in[4];
    const float* bout = (const float*)d_in[5];
    const float* g2   = (const float*)d_in[6];
    const float* b2   = (const float*)d_in[7];
    float* y = (float*)d_out;

    cudaFuncSetAttribute(la_pass1_kernel, cudaFuncAttributeMaxDynamicSharedMemorySize, P1_BYTES);
    cudaFuncSetAttribute(la_pass2_kernel, cudaFuncAttributeMaxDynamicSharedMemorySize, P2_BYTES);

    la_zero_kernel<<<33, 256>>>();
    la_pass1_kernel<<<dim3(NPOS / POSB, BB), TPB, P1_BYTES>>>(x, g1, b1, wqkv);
    la_fold_kernel<<<BB, 256>>>(wout);
    la_pass2_kernel<<<dim3(NPOS / POSB, BB), TPB, P2_BYTES>>>(x, g1, b1, wqkv, bout, g2, b2, y);
}